// round 15
// baseline (speedup 1.0000x reference)
#include <cuda_runtime.h>
#include <cuda_fp16.h>
#include <cstdint>
#include <cstddef>

#define BQ   16
#define HDIM 64
#define WDIM 64
#define CIN  256
#define COUT 256
#define NTAP 9

#define TH 16
#define TW 8
#define BK 64                      /* ci per stage (f16) */
#define NCHUNK (CIN/BK)            /* 4 */
#define NS (NTAP*NCHUNK)           /* 36 stages */
#define HP (TH+2)
#define WP (TW+2)
#define NPIX (HP*WP)               /* 180 halo pixels */
#define PITCH 144                  /* bytes per row: 128 data + 16 pad */
#define NPART (NTAP*16)            /* 144 demod partial groups */

/* dynamic smem layout (bytes) */
#define SM_DEMOD 0                          /* 128 f32 = 512 B */
#define SM_XS0   1024
#define XS_BYTES (NPIX*PITCH)               /* 25920 */
#define SM_XS1   (SM_XS0 + XS_BYTES)        /* 26944 */
#define SM_BS    (SM_XS1 + XS_BYTES)        /* 52864 */
#define BS_BYTES (128*PITCH)                /* 18432: 128 co rows */
#define SM_TOTAL (SM_BS + 3*BS_BYTES)       /* 108160 -> 2 CTAs/SM */

// Scratch (device globals; no runtime allocation)
__device__ __half g_xmod[(size_t)BQ*HDIM*WDIM*CIN];   // modulated x, f16 (32 MB)
__device__ __half g_wtT[(size_t)NTAP*COUT*CIN];       // f16 weights [tap][co][ci]
__device__ float  g_dp2[NPART*BQ*COUT];               // demod partials [part][b][co]
__device__ float  g_demod[BQ*COUT];

// ---------------- prep kernels ----------------

__global__ void prep_w_all(const float* __restrict__ kern,
                           const float* __restrict__ style) {
    __shared__ float s2[16][16];          // [b][i] = (style+1)^2
    int tap = blockIdx.x;
    int cig = blockIdx.y;
    int co  = threadIdx.x;
    {
        int b = threadIdx.x >> 4, i = threadIdx.x & 15;
        float s = style[b*CIN + cig*16 + i] + 1.0f;
        s2[b][i] = s*s;
    }
    __syncthreads();

    float  v2[16];
    __half h[16];
    #pragma unroll
    for (int i = 0; i < 16; ++i) {
        int ci = cig*16 + i;
        float v = kern[((size_t)(tap*CIN + ci))*COUT + co];   // coalesced over co
        h[i]  = __float2half_rn(v);
        v2[i] = v*v;
    }
    *reinterpret_cast<uint4*>(g_wtT + ((size_t)(tap*COUT + co))*CIN + cig*16) =
        *reinterpret_cast<const uint4*>(h);
    *reinterpret_cast<uint4*>(g_wtT + ((size_t)(tap*COUT + co))*CIN + cig*16 + 8) =
        *reinterpret_cast<const uint4*>(h + 8);

    const int part = tap*16 + cig;
    #pragma unroll
    for (int b = 0; b < BQ; ++b) {
        float a = 0.0f;
        #pragma unroll
        for (int i = 0; i < 16; ++i) a += s2[b][i] * v2[i];
        g_dp2[(size_t)part*(BQ*COUT) + b*COUT + co] = a;
    }
}

__global__ void prep_demod_red() {
    int b = blockIdx.x, co = threadIdx.x;
    float a = 0.0f;
    #pragma unroll 16
    for (int j = 0; j < NPART; ++j)
        a += g_dp2[(size_t)j*(BQ*COUT) + b*COUT + co];
    g_demod[b*COUT + co] = rsqrtf(a + 1e-8f);
}

__global__ void prep_x(const float* __restrict__ x,
                       const float* __restrict__ style) {
    int i0 = blockIdx.x * 256 + threadIdx.x;
    float4 v[4], s[4];
    #pragma unroll
    for (int j = 0; j < 4; ++j) {
        int i = i0 + j*1048576;
        int e = i << 2;
        int ci = e & (CIN - 1);
        int b  = e >> 20;
        v[j] = reinterpret_cast<const float4*>(x)[i];
        s[j] = reinterpret_cast<const float4*>(style)[(b*CIN + ci) >> 2];
    }
    #pragma unroll
    for (int j = 0; j < 4; ++j) {
        int i = i0 + j*1048576;
        __half2 h01 = __floats2half2_rn(v[j].x*(s[j].x+1.0f), v[j].y*(s[j].y+1.0f));
        __half2 h23 = __floats2half2_rn(v[j].z*(s[j].z+1.0f), v[j].w*(s[j].w+1.0f));
        uint2 pk;
        pk.x = *reinterpret_cast<uint32_t*>(&h01);
        pk.y = *reinterpret_cast<uint32_t*>(&h23);
        reinterpret_cast<uint2*>(g_xmod)[i] = pk;
    }
}

// ---------------- main implicit-GEMM conv (f16 mma, 4 warps, warp tile 64x64) ----------------

__global__ void __launch_bounds__(128, 2) modconv_kernel(float* __restrict__ out) {
    extern __shared__ char smem[];
    float* sdemod = reinterpret_cast<float*>(smem + SM_DEMOD);

    const int tid  = threadIdx.x;
    const int lane = tid & 31;
    const int wid  = tid >> 5;     // 0..3
    const int warp_m = wid >> 1;   // 0..1  (M 2x64)
    const int warp_n = wid & 1;    // 0..1  (N 2x64)
    const int gid = lane >> 2;
    const int tig = lane & 3;

    const int bt     = blockIdx.x;         // 1024 = 512 m-tiles * 2 n-tiles
    const int n_tile = bt & 1;
    const int mt     = bt >> 1;
    const int b      = mt >> 5;
    const int tI     = mt & 31;
    const int h0     = (tI >> 3) << 4;     // *16
    const int w0     = (tI & 7) << 3;      // *8
    const int co0    = n_tile << 7;        // *128

    const uint32_t sbase = (uint32_t)__cvta_generic_to_shared(smem);

    // ldmatrix A (.x4): lane supplies pixel row (lane&15), k-half (lane>>4)
    uint32_t a_off[4];
    #pragma unroll
    for (int mf = 0; mf < 4; ++mf) {
        int i  = warp_m*64 + mf*16 + (lane & 15);
        int hi = i >> 3, wi = i & 7;
        a_off[mf] = (uint32_t)(((hi + 1)*WP + (wi + 1)) * PITCH + (lane >> 4)*16);
    }
    // ldmatrix B (.x4): matrices = {n8lo@k0, n8lo@k8, n8hi@k0, n8hi@k8}
    const uint32_t b_off4 = (uint32_t)(
        (warp_n*64 + ((lane >> 4) & 1)*8 + (lane & 7)) * PITCH
        + ((lane >> 3) & 1)*16);

    sdemod[tid] = g_demod[b*COUT + co0 + tid];     // 128 cols for this CTA

    auto stage_x = [&](int chunk) {
        const uint32_t xb = sbase + ((chunk & 1) ? SM_XS1 : SM_XS0);
        const int ci0 = chunk * BK;
        #pragma unroll 1
        for (int t = tid; t < NPIX * 8; t += 128) {           // 1440 x 16B
            int pix = t >> 3;
            int c4  = t & 7;
            int hh  = pix / WP;
            int ww  = pix - hh * WP;
            int gh  = h0 - 1 + hh;
            int gw  = w0 - 1 + ww;
            bool ok = ((unsigned)gh < HDIM) && ((unsigned)gw < WDIM);
            const void* src = g_xmod;
            if (ok) src = g_xmod + ((size_t)((b*HDIM + gh)*WDIM + gw))*CIN + ci0 + c4*8;
            int sz = ok ? 16 : 0;
            uint32_t dst = xb + (uint32_t)(pix*PITCH + c4*16);
            asm volatile("cp.async.cg.shared.global [%0], [%1], 16, %2;\n"
                         :: "r"(dst), "l"(src), "r"(sz));
        }
    };

    auto stage_b = [&](int f) {
        int tap   = f % NTAP;
        int chunk = f / NTAP;
        uint32_t base = sbase + SM_BS + (f % 3)*BS_BYTES;
        #pragma unroll 1
        for (int t = tid; t < 128 * 8; t += 128) {            // 1024 x 16B
            int n  = t >> 3;
            int c4 = t & 7;
            const void* src = g_wtT + ((size_t)(tap*COUT + co0 + n))*CIN
                              + chunk*BK + c4*8;
            uint32_t dst = base + (uint32_t)(n*PITCH + c4*16);
            asm volatile("cp.async.cg.shared.global [%0], [%1], 16;\n"
                         :: "r"(dst), "l"(src));
        }
    };

    auto fill = [&](int f) {
        if ((f % NTAP) == 0) stage_x(f / NTAP);
        stage_b(f);
        asm volatile("cp.async.commit_group;\n");
    };

    float acc[4][8][4];
    #pragma unroll
    for (int mf = 0; mf < 4; ++mf)
        #pragma unroll
        for (int nf = 0; nf < 8; ++nf)
            #pragma unroll
            for (int r = 0; r < 4; ++r) acc[mf][nf][r] = 0.0f;

    fill(0);
    fill(1);

    #pragma unroll 1
    for (int s = 0; s < NS; ++s) {
        if (s + 2 < NS) asm volatile("cp.async.wait_group 1;\n");
        else            asm volatile("cp.async.wait_group 0;\n");
        // one barrier: stage-s data visible; stage s-1 compute done -> buffers reusable
        __syncthreads();

        if (s + 2 < NS) fill(s + 2);

        const int tap   = s % NTAP;
        const int chunk = s / NTAP;
        const uint32_t xsp = sbase + ((chunk & 1) ? SM_XS1 : SM_XS0);
        const uint32_t bsp = sbase + SM_BS + (s % 3)*BS_BYTES;
        const int toff = ((tap/3)*WP + (tap%3) - (WP + 1)) * PITCH;

        #pragma unroll
        for (int kk = 0; kk < BK/16; ++kk) {     // 4 k16 iterations
            const int koff = kk*32;
            uint32_t afr[4][4], bfr[8][2];
            #pragma unroll
            for (int mf = 0; mf < 4; ++mf) {
                uint32_t addr = xsp + a_off[mf] + (uint32_t)(toff + koff);
                asm volatile(
                    "ldmatrix.sync.aligned.m8n8.x4.shared.b16 {%0,%1,%2,%3}, [%4];"
                    : "=r"(afr[mf][0]), "=r"(afr[mf][1]),
                      "=r"(afr[mf][2]), "=r"(afr[mf][3])
                    : "r"(addr));
            }
            #pragma unroll
            for (int j = 0; j < 4; ++j) {        // each x4 covers 2 nf chunks
                uint32_t addr = bsp + b_off4 + (uint32_t)(j*16*PITCH + koff);
                asm volatile(
                    "ldmatrix.sync.aligned.m8n8.x4.shared.b16 {%0,%1,%2,%3}, [%4];"
                    : "=r"(bfr[2*j][0]), "=r"(bfr[2*j][1]),
                      "=r"(bfr[2*j+1][0]), "=r"(bfr[2*j+1][1])
                    : "r"(addr));
            }
            #pragma unroll
            for (int mf = 0; mf < 4; ++mf) {
                #pragma unroll
                for (int nf = 0; nf < 8; ++nf) {
                    asm volatile(
                        "mma.sync.aligned.m16n8k16.row.col.f32.f16.f16.f32 "
                        "{%0,%1,%2,%3}, {%4,%5,%6,%7}, {%8,%9}, {%0,%1,%2,%3};\n"
                        : "+f"(acc[mf][nf][0]), "+f"(acc[mf][nf][1]),
                          "+f"(acc[mf][nf][2]), "+f"(acc[mf][nf][3])
                        : "r"(afr[mf][0]), "r"(afr[mf][1]),
                          "r"(afr[mf][2]), "r"(afr[mf][3]),
                          "r"(bfr[nf][0]), "r"(bfr[nf][1]));
                }
            }
        }
    }

    // Epilogue: scale by demod, coalesced float2 stores
    #pragma unroll
    for (int mf = 0; mf < 4; ++mf) {
        int i0 = warp_m*64 + mf*16 + gid;
        int hi = i0 >> 3, wi = i0 & 7;
        size_t r0 = ((size_t)((b*HDIM + h0 + hi)*WDIM + (w0 + wi))) * COUT;
        size_t r1 = r0 + (size_t)WDIM * COUT;     // pixel i0+8 -> next image row
        #pragma unroll
        for (int nf = 0; nf < 8; ++nf) {
            int cl = warp_n*64 + nf*8 + 2*tig;    // local col 0..127
            float dx = sdemod[cl], dy = sdemod[cl + 1];
            int col = co0 + cl;
            float2 v;
            v.x = acc[mf][nf][0] * dx;
            v.y = acc[mf][nf][1] * dy;
            *reinterpret_cast<float2*>(out + r0 + col) = v;
            v.x = acc[mf][nf][2] * dx;
            v.y = acc[mf][nf][3] * dy;
            *reinterpret_cast<float2*>(out + r1 + col) = v;
        }
    }
}

// ---------------- launch ----------------

extern "C" void kernel_launch(void* const* d_in, const int* in_sizes, int n_in,
                              void* d_out, int out_size) {
    (void)in_sizes; (void)n_in; (void)out_size;
    const float* x     = (const float*)d_in[0];   // [16,64,64,256] f32
    const float* style = (const float*)d_in[1];   // [16,256] f32
    const float* kern  = (const float*)d_in[2];   // [3,3,256,256] f32
    float* out = (float*)d_out;                   // [16,64,64,256] f32

    cudaFuncSetAttribute(modconv_kernel,
                         cudaFuncAttributeMaxDynamicSharedMemorySize, SM_TOTAL);

    prep_x<<<4096, 256>>>(x, style);                         // 96 MB, MLP=4
    prep_w_all<<<dim3(NTAP, 16), COUT>>>(kern, style);       // 144 blocks
    prep_demod_red<<<BQ, COUT>>>();                          // 16 blocks
    modconv_kernel<<<(BQ*HDIM*WDIM/(TH*TW))*(COUT/128), 128, SM_TOTAL>>>(out);  // 1024 CTAs
}

// round 16
// speedup vs baseline: 1.5621x; 1.5621x over previous
#include <cuda_runtime.h>
#include <cuda_fp16.h>
#include <cstdint>
#include <cstddef>

#define BQ   16
#define HDIM 64
#define WDIM 64
#define CIN  256
#define COUT 256
#define NTAP 9

#define TH 16
#define TW 8
#define BK 64                      /* ci per stage (f16) */
#define NCHUNK (CIN/BK)            /* 4 */
#define NS (NTAP*NCHUNK)           /* 36 stages */
#define HP (TH+2)
#define WP (TW+2)
#define NPIX (HP*WP)               /* 180 halo pixels */
#define PITCH 144                  /* bytes per row: 128 data + 16 pad */
#define NPART (NTAP*16)            /* 144 demod partial groups */

/* dynamic smem layout (bytes) */
#define SM_DEMOD 0                          /* 256 f32 = 1024 B (two 128-col halves) */
#define SM_XS0   1024
#define XS_BYTES (NPIX*PITCH)               /* 25920 */
#define SM_XS1   (SM_XS0 + XS_BYTES)        /* 26944 */
#define SM_BS    (SM_XS1 + XS_BYTES)        /* 52864 */
#define BS_BYTES (128*PITCH)                /* 18432 */
#define SM_TOTAL (SM_BS + 3*BS_BYTES)       /* 108160 -> 2 CTAs/SM */

// Scratch (device globals; no runtime allocation)
__device__ __half g_xmod[(size_t)BQ*HDIM*WDIM*CIN];   // modulated x, f16 (32 MB)
__device__ __half g_wtT[(size_t)NTAP*COUT*CIN];       // f16 weights [tap][co][ci]
__device__ float  g_dp2[NPART*BQ*COUT];               // demod partials [part][b][co]

// ---------------- fused prep: x-modulate blocks + weight blocks ----------------

__global__ void prep_fused(const float* __restrict__ x,
                           const float* __restrict__ style,
                           const float* __restrict__ kern) {
    if (blockIdx.x < 4096) {
        // ---- x path: modulate + f16 convert, MLP=4 ----
        int i0 = blockIdx.x * 256 + threadIdx.x;
        float4 v[4], s[4];
        #pragma unroll
        for (int j = 0; j < 4; ++j) {
            int i = i0 + j*1048576;
            int e = i << 2;
            int ci = e & (CIN - 1);
            int b  = e >> 20;
            v[j] = reinterpret_cast<const float4*>(x)[i];
            s[j] = reinterpret_cast<const float4*>(style)[(b*CIN + ci) >> 2];
        }
        #pragma unroll
        for (int j = 0; j < 4; ++j) {
            int i = i0 + j*1048576;
            __half2 h01 = __floats2half2_rn(v[j].x*(s[j].x+1.0f), v[j].y*(s[j].y+1.0f));
            __half2 h23 = __floats2half2_rn(v[j].z*(s[j].z+1.0f), v[j].w*(s[j].w+1.0f));
            uint2 pk;
            pk.x = *reinterpret_cast<uint32_t*>(&h01);
            pk.y = *reinterpret_cast<uint32_t*>(&h23);
            reinterpret_cast<uint2*>(g_xmod)[i] = pk;
        }
    } else {
        // ---- w path: f16 transpose + demod partials ----
        __shared__ float s2[16][16];          // [b][i] = (style+1)^2
        int wb  = blockIdx.x - 4096;          // 0..143
        int tap = wb >> 4;
        int cig = wb & 15;
        int co  = threadIdx.x;
        {
            int b = threadIdx.x >> 4, i = threadIdx.x & 15;
            float s = style[b*CIN + cig*16 + i] + 1.0f;
            s2[b][i] = s*s;
        }
        __syncthreads();

        float  v2[16];
        __half h[16];
        #pragma unroll
        for (int i = 0; i < 16; ++i) {
            int ci = cig*16 + i;
            float v = kern[((size_t)(tap*CIN + ci))*COUT + co];   // coalesced over co
            h[i]  = __float2half_rn(v);
            v2[i] = v*v;
        }
        *reinterpret_cast<uint4*>(g_wtT + ((size_t)(tap*COUT + co))*CIN + cig*16) =
            *reinterpret_cast<const uint4*>(h);
        *reinterpret_cast<uint4*>(g_wtT + ((size_t)(tap*COUT + co))*CIN + cig*16 + 8) =
            *reinterpret_cast<const uint4*>(h + 8);

        const int part = tap*16 + cig;
        #pragma unroll
        for (int b = 0; b < BQ; ++b) {
            float a = 0.0f;
            #pragma unroll
            for (int i = 0; i < 16; ++i) a += s2[b][i] * v2[i];
            g_dp2[(size_t)part*(BQ*COUT) + b*COUT + co] = a;
        }
    }
}

// ---------------- main implicit-GEMM conv (mma.sync f16 + ldmatrix) ----------------

__global__ void __launch_bounds__(256, 2) modconv_kernel(float* __restrict__ out) {
    extern __shared__ char smem[];
    float* sdemod = reinterpret_cast<float*>(smem + SM_DEMOD);

    const int tid  = threadIdx.x;
    const int lane = tid & 31;
    const int wid  = tid >> 5;
    const int warp_m = wid >> 2;   // 0..1
    const int warp_n = wid & 3;    // 0..3
    const int gid = lane >> 2;
    const int tig = lane & 3;

    const int bt     = blockIdx.x;
    const int n_tile = bt & 1;
    const int mt     = bt >> 1;
    const int b      = mt >> 5;
    const int tI     = mt & 31;
    const int h0     = (tI >> 3) << 4;     // *16
    const int w0     = (tI & 7) << 3;      // *8
    const int co0    = n_tile << 7;        // *128

    const uint32_t sbase = (uint32_t)__cvta_generic_to_shared(smem);

    // ldmatrix A addresses
    uint32_t a_off[4];
    #pragma unroll
    for (int mf = 0; mf < 4; ++mf) {
        int i  = warp_m*64 + mf*16 + (lane & 15);
        int hi = i >> 3, wi = i & 7;
        a_off[mf] = (uint32_t)(((hi + 1)*WP + (wi + 1)) * PITCH + (lane >> 4)*16);
    }
    // ldmatrix B addresses
    uint32_t b_off[4];
    #pragma unroll
    for (int nf = 0; nf < 4; ++nf) {
        int n = warp_n*32 + nf*8 + (lane & 7);
        b_off[nf] = (uint32_t)(n*PITCH + ((lane >> 3) & 1)*16);
    }

    auto stage_x = [&](int chunk) {
        const uint32_t xb = sbase + ((chunk & 1) ? SM_XS1 : SM_XS0);
        const int ci0 = chunk * BK;
        #pragma unroll 1
        for (int t = tid; t < NPIX * 8; t += 256) {           // 1440 x 16B
            int pix = t >> 3;
            int c4  = t & 7;
            int hh  = pix / WP;
            int ww  = pix - hh * WP;
            int gh  = h0 - 1 + hh;
            int gw  = w0 - 1 + ww;
            bool ok = ((unsigned)gh < HDIM) && ((unsigned)gw < WDIM);
            const void* src = g_xmod;
            if (ok) src = g_xmod + ((size_t)((b*HDIM + gh)*WDIM + gw))*CIN + ci0 + c4*8;
            int sz = ok ? 16 : 0;
            uint32_t dst = xb + (uint32_t)(pix*PITCH + c4*16);
            asm volatile("cp.async.cg.shared.global [%0], [%1], 16, %2;\n"
                         :: "r"(dst), "l"(src), "r"(sz));
        }
    };

    auto stage_b = [&](int f) {
        int tap   = f % NTAP;
        int chunk = f / NTAP;
        uint32_t base = sbase + SM_BS + (f % 3)*BS_BYTES;
        #pragma unroll 1
        for (int t = tid; t < 128 * 8; t += 256) {            // 1024 x 16B
            int n  = t >> 3;
            int c4 = t & 7;
            const void* src = g_wtT + ((size_t)(tap*COUT + co0 + n))*CIN
                              + chunk*BK + c4*8;
            uint32_t dst = base + (uint32_t)(n*PITCH + c4*16);
            asm volatile("cp.async.cg.shared.global [%0], [%1], 16;\n"
                         :: "r"(dst), "l"(src));
        }
    };

    auto fill = [&](int f) {
        if ((f % NTAP) == 0) stage_x(f / NTAP);
        stage_b(f);
        asm volatile("cp.async.commit_group;\n");
    };

    float acc[4][4][4];
    #pragma unroll
    for (int mf = 0; mf < 4; ++mf)
        #pragma unroll
        for (int nf = 0; nf < 4; ++nf)
            #pragma unroll
            for (int r = 0; r < 4; ++r) acc[mf][nf][r] = 0.0f;

    fill(0);
    fill(1);

    // Demod partial reduction for this CTA's 128 cols, overlapped with the
    // prologue cp.asyncs. Threads 0-127 sum parts 0..71, threads 128-255 sum
    // 72..143; halves combined (+rsqrt) in the epilogue. First mainloop
    // __syncthreads orders these smem writes before any epilogue read.
    {
        const float* dp = g_dp2 + (size_t)((tid < 128) ? 0 : 72)*(BQ*COUT)
                          + b*COUT + co0 + (tid & 127);
        float a = 0.0f;
        #pragma unroll 8
        for (int j = 0; j < 72; ++j) a += dp[(size_t)j*(BQ*COUT)];
        sdemod[tid] = a;
    }

    #pragma unroll 1
    for (int s = 0; s < NS; ++s) {
        if (s + 2 < NS) asm volatile("cp.async.wait_group 1;\n");
        else            asm volatile("cp.async.wait_group 0;\n");
        // one barrier: stage-s data visible; stage s-1 compute done -> buffers reusable
        __syncthreads();

        if (s + 2 < NS) fill(s + 2);

        const int tap   = s % NTAP;
        const int chunk = s / NTAP;
        const uint32_t xsp = sbase + ((chunk & 1) ? SM_XS1 : SM_XS0);
        const uint32_t bsp = sbase + SM_BS + (s % 3)*BS_BYTES;
        const int toff = ((tap/3)*WP + (tap%3) - (WP + 1)) * PITCH;

        #pragma unroll
        for (int kk = 0; kk < BK/16; ++kk) {     // 4 k16 iterations
            const int koff = kk*32;
            uint32_t afr[4][4], bfr[4][2];
            #pragma unroll
            for (int mf = 0; mf < 4; ++mf) {
                uint32_t addr = xsp + a_off[mf] + (uint32_t)(toff + koff);
                asm volatile(
                    "ldmatrix.sync.aligned.m8n8.x4.shared.b16 {%0,%1,%2,%3}, [%4];"
                    : "=r"(afr[mf][0]), "=r"(afr[mf][1]),
                      "=r"(afr[mf][2]), "=r"(afr[mf][3])
                    : "r"(addr));
            }
            #pragma unroll
            for (int nf = 0; nf < 4; ++nf) {
                uint32_t addr = bsp + b_off[nf] + (uint32_t)koff;
                asm volatile(
                    "ldmatrix.sync.aligned.m8n8.x2.shared.b16 {%0,%1}, [%2];"
                    : "=r"(bfr[nf][0]), "=r"(bfr[nf][1])
                    : "r"(addr));
            }
            #pragma unroll
            for (int mf = 0; mf < 4; ++mf) {
                #pragma unroll
                for (int nf = 0; nf < 4; ++nf) {
                    asm volatile(
                        "mma.sync.aligned.m16n8k16.row.col.f32.f16.f16.f32 "
                        "{%0,%1,%2,%3}, {%4,%5,%6,%7}, {%8,%9}, {%0,%1,%2,%3};\n"
                        : "+f"(acc[mf][nf][0]), "+f"(acc[mf][nf][1]),
                          "+f"(acc[mf][nf][2]), "+f"(acc[mf][nf][3])
                        : "r"(afr[mf][0]), "r"(afr[mf][1]),
                          "r"(afr[mf][2]), "r"(afr[mf][3]),
                        "r"(bfr[nf][0]), "r"(bfr[nf][1]));
                }
            }
        }
    }

    // Epilogue: demod = rsqrt(lo+hi+eps), coalesced float2 stores
    float dxv[4], dyv[4];
    #pragma unroll
    for (int nf = 0; nf < 4; ++nf) {
        int cl = warp_n*32 + nf*8 + 2*tig;    // local col 0..127
        dxv[nf] = rsqrtf(sdemod[cl]     + sdemod[128 + cl]     + 1e-8f);
        dyv[nf] = rsqrtf(sdemod[cl + 1] + sdemod[128 + cl + 1] + 1e-8f);
    }
    #pragma unroll
    for (int mf = 0; mf < 4; ++mf) {
        int i0 = warp_m*64 + mf*16 + gid;
        int hi = i0 >> 3, wi = i0 & 7;
        size_t r0 = ((size_t)((b*HDIM + h0 + hi)*WDIM + (w0 + wi))) * COUT;
        size_t r1 = r0 + (size_t)WDIM * COUT;     // pixel i0+8 -> next image row
        #pragma unroll
        for (int nf = 0; nf < 4; ++nf) {
            int col = co0 + warp_n*32 + nf*8 + 2*tig;
            float2 v;
            v.x = acc[mf][nf][0] * dxv[nf];
            v.y = acc[mf][nf][1] * dyv[nf];
            *reinterpret_cast<float2*>(out + r0 + col) = v;
            v.x = acc[mf][nf][2] * dxv[nf];
            v.y = acc[mf][nf][3] * dyv[nf];
            *reinterpret_cast<float2*>(out + r1 + col) = v;
        }
    }
}

// ---------------- launch ----------------

extern "C" void kernel_launch(void* const* d_in, const int* in_sizes, int n_in,
                              void* d_out, int out_size) {
    (void)in_sizes; (void)n_in; (void)out_size;
    const float* x     = (const float*)d_in[0];   // [16,64,64,256] f32
    const float* style = (const float*)d_in[1];   // [16,256] f32
    const float* kern  = (const float*)d_in[2];   // [3,3,256,256] f32
    float* out = (float*)d_out;                   // [16,64,64,256] f32

    cudaFuncSetAttribute(modconv_kernel,
                         cudaFuncAttributeMaxDynamicSharedMemorySize, SM_TOTAL);

    prep_fused<<<4096 + NPART, 256>>>(x, style, kern);       // one prep launch
    modconv_kernel<<<(BQ*HDIM*WDIM/(TH*TW)) * (COUT/128), 256, SM_TOTAL>>>(out);
}